// round 14
// baseline (speedup 1.0000x reference)
#include <cuda_runtime.h>
#include <math.h>

#define BB 64
#define NN 16384
#define MM 128
#define CC 1024
#define EPSV 1e-16f
#define LAG 6                     // wread trails sim by LAG batches (48 MB < L2)
#define NGROUP (BB + LAG)         // 70 groups of 128 bids

// ---- scratch (device globals; statically zero-initialized) ----
__device__ float g_S[BB * NN];          // 4 MB: exp(beta*(sim-1))
__device__ float g_k[BB * MM];
__device__ float g_kn[BB];
__device__ float g_beta[BB], g_gate[BB], g_gamma[BB];
__device__ float g_shift[BB][3];
__device__ float g_Z[BB];               // softmax denominator (shift = beta)
__device__ float g_WZ[BB];              // sharpen denominator
__device__ unsigned int g_proj[BB];     // proj(b) done flag
__device__ unsigned int g_simctr[BB];   // sim blocks completed per batch
__device__ unsigned int g_wctr[BB];     // wread blocks completed per batch

__device__ __forceinline__ float softplus_f(float x) {
    return (x > 20.f) ? x : log1pf(expf(x));
}

// single fused kernel:
//   bids [0, 64)            : proj role, batch = bid
//   bids [64, 64+NGROUP*128): group g=(bid-64)>>7, h=(bid-64)&127
//       h <  64 : sim  role, batch g       (skip if g >= BB)
//       h >= 64 : wread role, batch g-LAG  (skip if <0)
__global__ void __launch_bounds__(256) k_all(
        const float* __restrict__ mem,
        const float* __restrict__ pw,
        const float* __restrict__ ctrl,
        const float* __restrict__ key_w, const float* __restrict__ key_b,
        const float* __restrict__ beta_w, const float* __restrict__ beta_b,
        const float* __restrict__ gate_w, const float* __restrict__ gate_b,
        const float* __restrict__ shift_w, const float* __restrict__ shift_b,
        const float* __restrict__ gamma_w, const float* __restrict__ gamma_b,
        float* __restrict__ out) {
    __shared__ float sh[256];
    __shared__ float4 sacc[256];
    __shared__ float swz[8];
    __shared__ unsigned int s_tick;
    __shared__ float sc[CC];
    __shared__ float kred[2][MM];
    __shared__ float r6[6][8];
    int bid = blockIdx.x;
    int t = threadIdx.x, warp = t >> 5, lane = t & 31;

    if (bid < BB) {
        // ================= PROJ role =================
        int b = bid;
        if (t < MM) out[(size_t)BB * NN + b * MM + t] = 0.f;   // zero read_vec slice
        for (int i = t; i < CC; i += 256) sc[i] = ctrl[b * CC + i];
        __syncthreads();

        int half = t >> 7, col = t & 127;
        float acc = 0.f;
        int c0 = half * 512;
        #pragma unroll 8
        for (int c = c0; c < c0 + 512; c++) acc += sc[c] * key_w[c * MM + col];
        kred[half][col] = acc;

        float a0 = 0, a1 = 0, a2 = 0, s0 = 0, s1 = 0, s2 = 0;
        for (int c = t; c < CC; c += 256) {
            float x = sc[c];
            a0 += x * beta_w[c];
            a1 += x * gate_w[c];
            a2 += x * gamma_w[c];
            s0 += x * shift_w[c * 3 + 0];
            s1 += x * shift_w[c * 3 + 1];
            s2 += x * shift_w[c * 3 + 2];
        }
        #pragma unroll
        for (int off = 16; off > 0; off >>= 1) {
            a0 += __shfl_down_sync(0xffffffffu, a0, off);
            a1 += __shfl_down_sync(0xffffffffu, a1, off);
            a2 += __shfl_down_sync(0xffffffffu, a2, off);
            s0 += __shfl_down_sync(0xffffffffu, s0, off);
            s1 += __shfl_down_sync(0xffffffffu, s1, off);
            s2 += __shfl_down_sync(0xffffffffu, s2, off);
        }
        if (lane == 0) {
            r6[0][warp] = a0; r6[1][warp] = a1; r6[2][warp] = a2;
            r6[3][warp] = s0; r6[4][warp] = s1; r6[5][warp] = s2;
        }
        __syncthreads();

        if (t < MM) {
            float kt = tanhf(kred[0][t] + kred[1][t] + key_b[t]);
            g_k[b * MM + t] = kt;
            sh[t] = kt * kt;
        }
        __syncthreads();
        for (int s = 64; s > 0; s >>= 1) {
            if (t < s) sh[t] += sh[t + s];
            __syncthreads();
        }
        if (t == 0) {
            g_kn[b] = sqrtf(sh[0]);
            float v[6];
            #pragma unroll
            for (int j = 0; j < 6; j++) {
                float sum = 0.f;
                #pragma unroll
                for (int w8 = 0; w8 < 8; w8++) sum += r6[j][w8];
                v[j] = sum;
            }
            g_beta[b]  = softplus_f(v[0] + beta_b[0]);
            g_gate[b]  = 1.f / (1.f + expf(-(v[1] + gate_b[0])));
            g_gamma[b] = 1.f + softplus_f(v[2] + gamma_b[0]);
            float v0 = v[3] + shift_b[0];
            float v1 = v[4] + shift_b[1];
            float v2 = v[5] + shift_b[2];
            float mx = fmaxf(v0, fmaxf(v1, v2));
            float e0 = expf(v0 - mx), e1 = expf(v1 - mx), e2 = expf(v2 - mx);
            float inv = 1.f / (e0 + e1 + e2);
            g_shift[b][0] = e0 * inv;
            g_shift[b][1] = e1 * inv;
            g_shift[b][2] = e2 * inv;
        }
        __threadfence();
        __syncthreads();
        if (t == 0) atomicExch(&g_proj[b], 1u);
        return;
    }

    int g = (bid - BB) >> 7, h = (bid - BB) & 127;

    if (h < 64) {
        // ================= SIM role: batch g, chunk h =================
        int b = g;
        if (b >= BB) return;
        // gate on proj(b)
        if (t == 0) {
            while (atomicAdd(&g_proj[b], 0u) == 0u) __nanosleep(64);
        }
        __syncthreads();
        __threadfence();

        int base = h * 256 + warp * 32;
        int sub = lane & 7, rg = lane >> 3;
        if (t < MM) sh[t] = g_k[b * MM + t];
        __syncthreads();
        const float4* skp = (const float4*)sh;
        float4 kq0 = skp[sub], kq1 = skp[sub + 8], kq2 = skp[sub + 16], kq3 = skp[sub + 24];
        float beta = g_beta[b], kn = g_kn[b];
        float zsum = 0.f;
        const float4* mp = (const float4*)(mem + (size_t)b * NN * MM);

        #pragma unroll 4
        for (int j = 0; j < 8; j++) {
            int row = base + j * 4 + rg;
            const float4* rp = mp + (size_t)row * 32;
            // cached loads: keep resident in L2 for the trailing wread
            float4 v0 = __ldg(rp + sub),      v1 = __ldg(rp + sub + 8);
            float4 v2 = __ldg(rp + sub + 16), v3 = __ldg(rp + sub + 24);
            float dot = v0.x * kq0.x + v0.y * kq0.y + v0.z * kq0.z + v0.w * kq0.w
                      + v1.x * kq1.x + v1.y * kq1.y + v1.z * kq1.z + v1.w * kq1.w
                      + v2.x * kq2.x + v2.y * kq2.y + v2.z * kq2.z + v2.w * kq2.w
                      + v3.x * kq3.x + v3.y * kq3.y + v3.z * kq3.z + v3.w * kq3.w;
            float nrm = v0.x * v0.x + v0.y * v0.y + v0.z * v0.z + v0.w * v0.w
                      + v1.x * v1.x + v1.y * v1.y + v1.z * v1.z + v1.w * v1.w
                      + v2.x * v2.x + v2.y * v2.y + v2.z * v2.z + v2.w * v2.w
                      + v3.x * v3.x + v3.y * v3.y + v3.z * v3.z + v3.w * v3.w;
            #pragma unroll
            for (int off = 4; off > 0; off >>= 1) {
                dot += __shfl_down_sync(0xffffffffu, dot, off);
                nrm += __shfl_down_sync(0xffffffffu, nrm, off);
            }
            if (sub == 0) {
                float s = beta * dot / (kn * sqrtf(nrm) + EPSV);
                float e = __expf(s - beta);
                g_S[b * NN + row] = e;
                zsum += e;
            }
        }
        zsum += __shfl_down_sync(0xffffffffu, zsum, 16);
        zsum += __shfl_down_sync(0xffffffffu, zsum, 8);
        if (lane == 0) atomicAdd(&g_Z[b], zsum);
        __threadfence();
        __syncthreads();
        if (t == 0) atomicAdd(&g_simctr[b], 1u);
    } else {
        // ================= WREAD role: batch g-LAG, chunk h-64 =================
        int b = g - LAG;
        if (b < 0) return;
        int base = (h - 64) * 256;
        int n = base + t;
        int nm = (n - 1) & (NN - 1), np = (n + 1) & (NN - 1);
        const float* pwb = pw + (size_t)b * NN;
        float pm = __ldg(pwb + nm), pc = __ldg(pwb + n), pl = __ldg(pwb + np);

        // wait for sim(b) completion (normally already done: LAG*128 bids behind)
        if (t == 0) {
            while (atomicAdd(&g_simctr[b], 0u) < 64u) __nanosleep(64);
        }
        __syncthreads();
        __threadfence();

        float gate = g_gate[b], og = 1.f - gate;
        float invZ = 1.f / g_Z[b];
        float s0 = g_shift[b][0], s1 = g_shift[b][1], s2 = g_shift[b][2];
        float gamma = g_gamma[b];
        const float* Sb = g_S + (size_t)b * NN;
        float wm = gate * Sb[nm] * invZ + og * pm;
        float wc = gate * Sb[n]  * invZ + og * pc;
        float wl = gate * Sb[np] * invZ + og * pl;
        float ws = s0 * wm + s1 * wc + s2 * wl;
        float wp = __powf(ws, gamma);
        out[(size_t)b * NN + n] = wp;   // unnormalized; ticket block rescales
        sh[t] = wp;

        float z = wp;
        #pragma unroll
        for (int off = 16; off > 0; off >>= 1) z += __shfl_down_sync(0xffffffffu, z, off);
        if (lane == 0) swz[warp] = z;
        __syncthreads();
        if (t == 0) {
            float s = swz[0];
            #pragma unroll
            for (int w8 = 1; w8 < 8; w8++) s += swz[w8];
            atomicAdd(&g_WZ[b], s);
        }

        // weighted read: mostly L2 hits (streamed by sim(b) LAG groups earlier)
        const float4* mp = (const float4*)(mem + ((size_t)b * NN + base + warp * 32) * MM);
        const float* swp = sh + warp * 32;
        float4 acc = make_float4(0.f, 0.f, 0.f, 0.f);
        #pragma unroll 4
        for (int i = 0; i < 32; i++) {
            float4 v = __ldcs(mp + (size_t)i * 32 + lane);   // last use: evict-first
            float wi = swp[i];
            acc.x += wi * v.x; acc.y += wi * v.y;
            acc.z += wi * v.z; acc.w += wi * v.w;
        }
        sacc[t] = acc;
        __syncthreads();
        if (t < 32) {
            float4 s = sacc[t];
            #pragma unroll
            for (int w8 = 1; w8 < 8; w8++) {
                float4 o = sacc[w8 * 32 + t];
                s.x += o.x; s.y += o.y; s.z += o.z; s.w += o.w;
            }
            float* rd = out + (size_t)BB * NN + b * MM + t * 4;
            atomicAdd(rd + 0, s.x);
            atomicAdd(rd + 1, s.y);
            atomicAdd(rd + 2, s.z);
            atomicAdd(rd + 3, s.w);
        }

        // ticket: last wread block of batch b normalizes + resets counters
        __threadfence();
        __syncthreads();
        if (t == 0) s_tick = atomicAdd(&g_wctr[b], 1u);
        __syncthreads();
        if (s_tick == 63u) {
            __threadfence();
            float inv = 1.f / (g_WZ[b] + EPSV);
            float4* wb = (float4*)(out + (size_t)b * NN);
            #pragma unroll 4
            for (int i = t; i < NN / 4; i += 256) {
                float4 v = wb[i];
                v.x *= inv; v.y *= inv; v.z *= inv; v.w *= inv;
                wb[i] = v;
            }
            if (t < 32) {
                float4* rv = (float4*)(out + (size_t)BB * NN + b * MM);
                float4 v = rv[t];
                v.x *= inv; v.y *= inv; v.z *= inv; v.w *= inv;
                rv[t] = v;
            }
            // re-arm per-batch state for the next graph replay
            __syncthreads();
            if (t == 0) {
                g_Z[b] = 0.f;
                g_WZ[b] = 0.f;
                g_proj[b] = 0u;
                g_simctr[b] = 0u;
                g_wctr[b] = 0u;
            }
        }
    }
}

extern "C" void kernel_launch(void* const* d_in, const int* in_sizes, int n_in,
                              void* d_out, int out_size) {
    const float* ctrl    = (const float*)d_in[0];
    const float* pw      = (const float*)d_in[1];
    const float* mem     = (const float*)d_in[2];
    const float* key_w   = (const float*)d_in[3];
    const float* key_b   = (const float*)d_in[4];
    const float* beta_w  = (const float*)d_in[5];
    const float* beta_b  = (const float*)d_in[6];
    const float* gate_w  = (const float*)d_in[7];
    const float* gate_b  = (const float*)d_in[8];
    const float* shift_w = (const float*)d_in[9];
    const float* shift_b = (const float*)d_in[10];
    const float* gamma_w = (const float*)d_in[11];
    const float* gamma_b = (const float*)d_in[12];
    // d_in[13..16] = erase_w/b, add_w/b — unused by the output, skipped.
    float* out = (float*)d_out;

    k_all<<<BB + NGROUP * 128, 256>>>(mem, pw, ctrl,
                                      key_w, key_b, beta_w, beta_b,
                                      gate_w, gate_b, shift_w, shift_b,
                                      gamma_w, gamma_b, out);
}